// round 14
// baseline (speedup 1.0000x reference)
#include <cuda_runtime.h>
#include <cuda_fp16.h>
#include <math.h>
#include <stdint.h>

#define D_MODEL 1024
#define NH      16
#define DK      64
#define DFF     4096
#define BATCH   2
#define SEQ     2048
#define MROWS   (BATCH*SEQ)   // 4096

// ---------------- scratch (device globals; no allocation allowed) ----------
__device__ __half h_xln[MROWS*D_MODEL];
__device__ __half h_q  [MROWS*D_MODEL];
__device__ __half h_k  [MROWS*D_MODEL];
__device__ __half h_v  [MROWS*D_MODEL];
__device__ __half h_ctx[MROWS*D_MODEL];
__device__ __half h_x2 [MROWS*D_MODEL];
__device__ __half h_ffh[MROWS*DFF];
__device__ float  g_out1[MROWS*D_MODEL];
// fp16 weights
__device__ __half h_wq[D_MODEL*D_MODEL];
__device__ __half h_wk[D_MODEL*D_MODEL];
__device__ __half h_wv[D_MODEL*D_MODEL];
__device__ __half h_wo[D_MODEL*D_MODEL];
__device__ __half h_w1[DFF*D_MODEL];
__device__ __half h_w2[D_MODEL*DFF];

// ---------------- helpers --------------------------------------------------
static __device__ __forceinline__ uint32_t smem_u32(const void* p) {
    uint32_t a;
    asm("{ .reg .u64 t; cvta.to.shared.u64 t, %1; cvt.u32.u64 %0, t; }"
        : "=r"(a) : "l"(p));
    return a;
}

static __device__ __forceinline__ uint32_t h2u(__half2 h) {
    union { __half2 h; uint32_t u; } x; x.h = h; return x.u;
}

static __device__ __forceinline__ float ex2(float x) {
    float y;
    asm("ex2.approx.ftz.f32 %0, %1;" : "=f"(y) : "f"(x));
    return y;
}

static __device__ __forceinline__ void mma_f16(
    float& c0, float& c1, float& c2, float& c3,
    uint32_t a0, uint32_t a1, uint32_t a2, uint32_t a3,
    uint32_t b0, uint32_t b1)
{
    asm volatile(
        "mma.sync.aligned.m16n8k16.row.col.f32.f16.f16.f32 "
        "{%0,%1,%2,%3}, {%4,%5,%6,%7}, {%8,%9}, {%0,%1,%2,%3};"
        : "+f"(c0), "+f"(c1), "+f"(c2), "+f"(c3)
        : "r"(a0), "r"(a1), "r"(a2), "r"(a3), "r"(b0), "r"(b1));
}

#define LDMX4(r0,r1,r2,r3,a) \
    asm volatile("ldmatrix.sync.aligned.m8n8.x4.shared.b16 {%0,%1,%2,%3}, [%4];" \
        : "=r"(r0),"=r"(r1),"=r"(r2),"=r"(r3) : "r"(a))
#define LDMX4T(r0,r1,r2,r3,a) \
    asm volatile("ldmatrix.sync.aligned.m8n8.x4.trans.shared.b16 {%0,%1,%2,%3}, [%4];" \
        : "=r"(r0),"=r"(r1),"=r"(r2),"=r"(r3) : "r"(a))

#define CP_ASYNC16(dst, src) \
    asm volatile("cp.async.cg.shared.global [%0], [%1], 16;" :: "r"(dst), "l"(src))

// 0.125 * log2(e): folded into Q so softmax is a bare ex2
#define QSCALE 0.18033688011112042f

// ---------------- fused: weight fp32->fp16 conversion + LN1 ----------------
#define WSEG  (D_MODEL*D_MODEL/4)
#define WBIG  (DFF*D_MODEL/4)
#define WTOT  (4*WSEG + 2*WBIG)
#define LN_BLOCKS   MROWS          // 4096
#define RW_BLOCKS   2048
#define FUSED_BLOCKS (LN_BLOCKS + RW_BLOCKS)

__global__ void __launch_bounds__(256) prep_kernel(
    const float* __restrict__ src, __half* __restrict__ xln,
    const float* __restrict__ alpha, const float* __restrict__ beta,
    const float4* __restrict__ wq, const float4* __restrict__ wk,
    const float4* __restrict__ wv, const float4* __restrict__ wo,
    const float4* __restrict__ w1, const float4* __restrict__ w2)
{
    if (blockIdx.x < LN_BLOCKS) {
        // ---- LayerNorm row (torch: ddof=1, eps added to std) ----
        int row = blockIdx.x;
        const float4* xr = (const float4*)(src + (size_t)row * D_MODEL);
        float4 v = xr[threadIdx.x];
        float s  = v.x + v.y + v.z + v.w;
        float sq = v.x*v.x + v.y*v.y + v.z*v.z + v.w*v.w;

        __shared__ float red[18];
        #pragma unroll
        for (int o = 16; o; o >>= 1) {
            s  += __shfl_xor_sync(0xffffffffu, s,  o);
            sq += __shfl_xor_sync(0xffffffffu, sq, o);
        }
        int w = threadIdx.x >> 5;
        if ((threadIdx.x & 31) == 0) { red[w] = s; red[8 + w] = sq; }
        __syncthreads();
        if (threadIdx.x == 0) {
            float ts = 0.f, tq = 0.f;
            #pragma unroll
            for (int i = 0; i < 8; i++) { ts += red[i]; tq += red[8 + i]; }
            red[16] = ts; red[17] = tq;
        }
        __syncthreads();
        float ts = red[16], tq = red[17];

        float mean = ts * (1.0f / D_MODEL);
        float var  = (tq - ts * mean) * (1.0f / (D_MODEL - 1));
        var = fmaxf(var, 0.0f);
        float denom = sqrtf(var) + 1e-6f;
        float a  = alpha[0], be = beta[0];
        float r  = a / denom;

        __half* yr = xln + (size_t)row * D_MODEL + threadIdx.x * 4;
        *(__half2*)(yr)     = __floats2half2_rn((v.x - mean) * r + be, (v.y - mean) * r + be);
        *(__half2*)(yr + 2) = __floats2half2_rn((v.z - mean) * r + be, (v.w - mean) * r + be);
    } else {
        // ---- weight rounding ----
        int bid = blockIdx.x - LN_BLOCKS;
        for (int i = bid * blockDim.x + threadIdx.x; i < WTOT;
             i += RW_BLOCKS * blockDim.x) {
            const float4* s; __half* d; int off;
            if      (i < 1*WSEG) { s = wq; d = h_wq; off = i; }
            else if (i < 2*WSEG) { s = wk; d = h_wk; off = i - 1*WSEG; }
            else if (i < 3*WSEG) { s = wv; d = h_wv; off = i - 2*WSEG; }
            else if (i < 4*WSEG) { s = wo; d = h_wo; off = i - 3*WSEG; }
            else if (i < 4*WSEG + WBIG) { s = w1; d = h_w1; off = i - 4*WSEG; }
            else                 { s = w2; d = h_w2; off = i - 4*WSEG - WBIG; }
            float4 v = s[off];
            *(__half2*)(d + 4*off)     = __floats2half2_rn(v.x, v.y);
            *(__half2*)(d + 4*off + 2) = __floats2half2_rn(v.z, v.w);
        }
    }
}

// ======================= Tensor-core FP16 GEMM ============================
// C[M,N] = A[M,K] * B[N,K]^T; CTA 128x128x32; 8 warps 2x4 (warp 64x32);
// 3-stage cp.async; ldmatrix fragments; 2 CTAs/SM. (R12 measured-best.)
#define GBM 128
#define GBN 128
#define GBK 32
#define HP 40
#define A_HALVES (GBM*HP)
#define B_HALVES (GBN*HP)
#define STG_HALVES (A_HALVES + B_HALVES)         // 10240
#define NSTAGE 3
#define GEMM_SMEM (NSTAGE*STG_HALVES*2)          // 61440 B

// EPI: 0 = half store (*QSCALE when z==0), 1 = bias+relu half,
//      2 = bias+residual float, 3 = residual float
template<int EPI>
__global__ void __launch_bounds__(256, 2) hgemm(
    const __half* __restrict__ A,
    const __half* __restrict__ B0, const __half* __restrict__ B1, const __half* __restrict__ B2,
    void* __restrict__ C0, void* __restrict__ C1, void* __restrict__ C2,
    const float* __restrict__ bias, const float* __restrict__ res,
    int M, int N, int K)
{
    extern __shared__ __half smh[];
    uint32_t sbase = smem_u32(smh);

    const __half* Bm = B0; void* Cm = C0;
    if (blockIdx.z == 1) { Bm = B1; Cm = C1; }
    else if (blockIdx.z == 2) { Bm = B2; Cm = C2; }

    int tid  = threadIdx.x;
    int lane = tid & 31, wid = tid >> 5;
    int warp_m = (wid >> 2) * 64;      // 0 / 64
    int warp_n = (wid & 3) * 32;       // 0,32,64,96
    int rowBase = blockIdx.y * GBM;
    int colBase = blockIdx.x * GBN;
    int r4 = lane >> 2, c4 = lane & 3;
    int lg = lane >> 3, li = lane & 7;

    uint32_t aLm = (uint32_t)(((lg & 1) * 8 + li) * HP + (lg >> 1) * 8) * 2u;
    uint32_t bLm = (uint32_t)(((lg >> 1) * 8 + li) * HP + (lg & 1) * 8) * 2u;

    const __half* Ag[2]; uint32_t aOff[2];
    #pragma unroll
    for (int j = 0; j < 2; j++) {
        int slot = tid + 256 * j;
        int r = slot >> 2, c = (slot & 3) * 8;
        Ag[j] = A + (size_t)(rowBase + r) * K + c;
        aOff[j] = (uint32_t)(r * HP + c) * 2u;
    }
    const __half* Bg[2]; uint32_t bOff[2];
    #pragma unroll
    for (int j = 0; j < 2; j++) {
        int slot = tid + 256 * j;
        int r = slot >> 2, c = (slot & 3) * 8;
        Bg[j] = Bm + (size_t)(colBase + r) * K + c;
        bOff[j] = (uint32_t)(r * HP + c) * 2u;
    }

    auto issue_tile = [&](int tt, int stage) {
        int k0 = tt * GBK;
        uint32_t sA = sbase + (uint32_t)stage * (STG_HALVES * 2u);
        uint32_t sB = sA + A_HALVES * 2u;
        #pragma unroll
        for (int j = 0; j < 2; j++) CP_ASYNC16(sA + aOff[j], Ag[j] + k0);
        #pragma unroll
        for (int j = 0; j < 2; j++) CP_ASYNC16(sB + bOff[j], Bg[j] + k0);
    };

    float acc[4][4][4];
    #pragma unroll
    for (int i = 0; i < 4; i++)
        #pragma unroll
        for (int j = 0; j < 4; j++)
            #pragma unroll
            for (int e = 0; e < 4; e++) acc[i][j][e] = 0.f;

    int T = K / GBK;
    issue_tile(0, 0);
    asm volatile("cp.async.commit_group;");
    issue_tile(1, 1);
    asm volatile("cp.async.commit_group;");

    int st_c = 0, st_l = 2;
    for (int t = 0; t < T; t++) {
        asm volatile("cp.async.wait_group 1;");
        __syncthreads();

        int nt = t + 2;
        int tt = (nt >= T) ? nt - T : nt;
        issue_tile(tt, st_l);
        asm volatile("cp.async.commit_group;");
        st_l = (st_l == 2) ? 0 : st_l + 1;

        uint32_t sA = sbase + (uint32_t)st_c * (STG_HALVES * 2u);
        uint32_t sB = sA + A_HALVES * 2u;
        st_c = (st_c == 2) ? 0 : st_c + 1;

        uint32_t aBase = sA + aLm + (uint32_t)(warp_m * HP) * 2u;
        uint32_t bBase = sB + bLm + (uint32_t)(warp_n * HP) * 2u;

        #pragma unroll
        for (int kk = 0; kk < 2; kk++) {
            uint32_t kByte = (uint32_t)(kk * 16) * 2u;
            uint32_t af[4][4], bf[4][2];
            #pragma unroll
            for (int i = 0; i < 4; i++)
                LDMX4(af[i][0], af[i][1], af[i][2], af[i][3],
                      aBase + (uint32_t)(i * 16 * HP) * 2u + kByte);
            #pragma unroll
            for (int jp = 0; jp < 2; jp++)
                LDMX4(bf[2*jp][0], bf[2*jp][1], bf[2*jp+1][0], bf[2*jp+1][1],
                      bBase + (uint32_t)(jp * 16 * HP) * 2u + kByte);
            #pragma unroll
            for (int i = 0; i < 4; i++)
                #pragma unroll
                for (int j = 0; j < 4; j++)
                    mma_f16(acc[i][j][0], acc[i][j][1], acc[i][j][2], acc[i][j][3],
                            af[i][0], af[i][1], af[i][2], af[i][3],
                            bf[j][0], bf[j][1]);
        }
    }

    float qs = 1.0f;
    if (EPI == 0 && blockIdx.z == 0) qs = QSCALE;

    #pragma unroll
    for (int i = 0; i < 4; i++) {
        int row = rowBase + warp_m + i * 16 + r4;
        #pragma unroll
        for (int j = 0; j < 4; j++) {
            int col = colBase + warp_n + j * 8 + c4 * 2;
            float2 lo = make_float2(acc[i][j][0], acc[i][j][1]);
            float2 hi = make_float2(acc[i][j][2], acc[i][j][3]);
            if (EPI == 0) {
                __half* Ch = (__half*)Cm;
                *(__half2*)&Ch[(size_t)row * N + col] =
                    __floats2half2_rn(lo.x * qs, lo.y * qs);
                *(__half2*)&Ch[(size_t)(row + 8) * N + col] =
                    __floats2half2_rn(hi.x * qs, hi.y * qs);
            } else if (EPI == 1) {
                float2 bi = *(const float2*)&bias[col];
                __half* Ch = (__half*)Cm;
                *(__half2*)&Ch[(size_t)row * N + col] =
                    __floats2half2_rn(fmaxf(lo.x + bi.x, 0.f), fmaxf(lo.y + bi.y, 0.f));
                *(__half2*)&Ch[(size_t)(row + 8) * N + col] =
                    __floats2half2_rn(fmaxf(hi.x + bi.x, 0.f), fmaxf(hi.y + bi.y, 0.f));
            } else if (EPI == 2) {
                float2 bi = *(const float2*)&bias[col];
                float2 r0 = *(const float2*)&res[(size_t)row * N + col];
                float2 r1 = *(const float2*)&res[(size_t)(row + 8) * N + col];
                float* Cf = (float*)Cm;
                *(float2*)&Cf[(size_t)row * N + col] =
                    make_float2(lo.x + bi.x + r0.x, lo.y + bi.y + r0.y);
                *(float2*)&Cf[(size_t)(row + 8) * N + col] =
                    make_float2(hi.x + bi.x + r1.x, hi.y + bi.y + r1.y);
            } else {
                float2 r0 = *(const float2*)&res[(size_t)row * N + col];
                float2 r1 = *(const float2*)&res[(size_t)(row + 8) * N + col];
                float* Cf = (float*)Cm;
                *(float2*)&Cf[(size_t)row * N + col]       = make_float2(lo.x + r0.x, lo.y + r0.y);
                *(float2*)&Cf[(size_t)(row + 8) * N + col] = make_float2(hi.x + r1.x, hi.y + r1.y);
            }
        }
    }
}

// ---------------- LayerNorm (torch: ddof=1, eps added to std) --------------
__global__ void __launch_bounds__(256) ln_kernel(
    const float* __restrict__ x, __half* __restrict__ y,
    const float* __restrict__ alpha, const float* __restrict__ beta)
{
    int row = blockIdx.x;
    const float4* xr = (const float4*)(x + (size_t)row * D_MODEL);
    float4 v = xr[threadIdx.x];
    float s  = v.x + v.y + v.z + v.w;
    float sq = v.x*v.x + v.y*v.y + v.z*v.z + v.w*v.w;

    __shared__ float red[18];
    #pragma unroll
    for (int o = 16; o; o >>= 1) {
        s  += __shfl_xor_sync(0xffffffffu, s,  o);
        sq += __shfl_xor_sync(0xffffffffu, sq, o);
    }
    int w = threadIdx.x >> 5;
    if ((threadIdx.x & 31) == 0) { red[w] = s; red[8 + w] = sq; }
    __syncthreads();
    if (threadIdx.x == 0) {
        float ts = 0.f, tq = 0.f;
        #pragma unroll
        for (int i = 0; i < 8; i++) { ts += red[i]; tq += red[8 + i]; }
        red[16] = ts; red[17] = tq;
    }
    __syncthreads();
    float ts = red[16], tq = red[17];

    float mean = ts * (1.0f / D_MODEL);
    float var  = (tq - ts * mean) * (1.0f / (D_MODEL - 1));
    var = fmaxf(var, 0.0f);
    float denom = sqrtf(var) + 1e-6f;
    float a  = alpha[0], be = beta[0];
    float r  = a / denom;

    __half* yr = y + (size_t)row * D_MODEL + threadIdx.x * 4;
    *(__half2*)(yr)     = __floats2half2_rn((v.x - mean) * r + be, (v.y - mean) * r + be);
    *(__half2*)(yr + 2) = __floats2half2_rn((v.z - mean) * r + be, (v.w - mean) * r + be);
}

// ============== Flash attention, fp16 mma + ldmatrix ======================
// 4-stage KV ring, single barrier per tile; Q pre-scaled; bare ex2 softmax.
// (R12 measured-best configuration.)
#define BQ  128
#define BKV 64
#define NKV 4
#define QP  72
#define KP  72
#define VP  72
#define ATTN_SMEM ((BQ*QP + NKV*BKV*KP + NKV*BKV*VP)*2 + NKV*64*4 + 8*4)

__global__ void __launch_bounds__(256, 2) attn_mma(
    const __half* __restrict__ q, const __half* __restrict__ k,
    const __half* __restrict__ v, const int* __restrict__ mask,
    __half* __restrict__ ctx)
{
    extern __shared__ __half sa[];
    __half* Qs = sa;                       // [128][72]
    __half* Ks = Qs + BQ*QP;               // NKV x [64][72]
    __half* Vs = Ks + NKV*BKV*KP;          // NKV x [64][72]
    int*    ms = (int*)(Vs + NKV*BKV*VP);  // NKV x [64]
    int*    fl = ms + NKV*64;              // 2 flags per stage

    int tid = threadIdx.x, lane = tid & 31, wid = tid >> 5;
    int r4 = lane >> 2, c4 = lane & 3;
    int lg = lane >> 3, li = lane & 7;
    int qt = blockIdx.x, h = blockIdx.y, b = blockIdx.z;
    int qbase = qt * BQ;
    int wq = wid * 16;

    const __half* qp = q + (size_t)(b * SEQ) * D_MODEL + h * DK;
    const __half* kp = k + (size_t)(b * SEQ) * D_MODEL + h * DK;
    const __half* vp = v + (size_t)(b * SEQ) * D_MODEL + h * DK;
    const int* maskb = mask + b * SEQ;

    uint32_t kLm = (uint32_t)(((lg >> 1) * 8 + li) * KP + (lg & 1) * 8) * 2u;
    uint32_t vLm = (uint32_t)(((lg & 1) * 8 + li) * VP + (lg >> 1) * 8) * 2u;

    #pragma unroll
    for (int i = 0; i < 4; i++) {
        int slot = tid + i * 256;
        int r = slot >> 3, c = (slot & 7) * 8;
        *(uint4*)&Qs[r * QP + c] = *(const uint4*)(qp + (size_t)(qbase + r) * D_MODEL + c);
    }

    uint32_t ksb = smem_u32(Ks), vsb = smem_u32(Vs);
    auto issue = [&](int tt) {
        int buf = tt & (NKV - 1), kv0 = tt * BKV;
        #pragma unroll
        for (int i = 0; i < 4; i++) {
            int slot = tid + i * 256;
            int r = (slot & 511) >> 3, c = (slot & 7) * 8;
            if (slot < 512)
                CP_ASYNC16(ksb + (uint32_t)(buf*BKV*KP + r*KP + c)*2u,
                           kp + (size_t)(kv0 + r) * D_MODEL + c);
            else
                CP_ASYNC16(vsb + (uint32_t)(buf*BKV*VP + r*VP + c)*2u,
                           vp + (size_t)(kv0 + r) * D_MODEL + c);
        }
        asm volatile("cp.async.commit_group;");
    };

    issue(0);
    issue(1);
    issue(2);
    if (tid < 192) {
        int m = maskb[tid];
        ms[tid] = m;
        int all = __all_sync(0xffffffffu, m != 0);
        if ((tid & 31) == 0) fl[tid >> 5] = all;
    }
    __syncthreads();

    uint32_t afq[4][4];
    {
        const __half* qrow = Qs + wq * QP + 2 * c4;
        #pragma unroll
        for (int kk = 0; kk < 4; kk++) {
            int k16 = kk * 16;
            afq[kk][0] = h2u(*(const __half2*)(qrow + (r4    ) * QP + k16));
            afq[kk][1] = h2u(*(const __half2*)(qrow + (r4 + 8) * QP + k16));
            afq[kk][2] = h2u(*(const __half2*)(qrow + (r4    ) * QP + k16 + 8));
            afq[kk][3] = h2u(*(const __half2*)(qrow + (r4 + 8) * QP + k16 + 8));
        }
    }

    float m0 = -1e30f, m1 = -1e30f, l0 = 0.f, l1 = 0.f;
    float oacc[8][4];
    #pragma unroll
    for (int j = 0; j < 8; j++)
        #pragma unroll
        for (int e = 0; e < 4; e++) oacc[j][e] = 0.f;

    const int T = SEQ / BKV;   // 32
    for (int t = 0; t < T; t++) {
        int buf = t & (NKV - 1);
        asm volatile("cp.async.wait_group 2;");
        __syncthreads();

        if (t + 3 < T) {
            issue(t + 3);
            if (tid < 64) {
                int st = (t + 3) & (NKV - 1);
                int m = maskb[(t + 3) * BKV + tid];
                ms[st * 64 + tid] = m;
                int all = __all_sync(0xffffffffu, m != 0);
                if ((tid & 31) == 0) fl[st * 2 + (tid >> 5)] = all;
            }
        }

        uint32_t kb = ksb + (uint32_t)(buf * BKV * KP) * 2u + kLm;
        uint32_t vb = vsb + (uint32_t)(buf * BKV * VP) * 2u + vLm;
        const int* mb = ms + buf * 64;
        bool allone = fl[buf * 2] && fl[buf * 2 + 1];

        float sacc[8][4];
        #pragma unroll
        for (int j = 0; j < 8; j++)
            #pragma unroll
            for (int e = 0; e < 4; e++) sacc[j][e] = 0.f;

        #pragma unroll
        for (int jp = 0; jp < 4; jp++) {
            uint32_t kaddr = kb + (uint32_t)(jp * 16 * KP) * 2u;
            #pragma unroll
            for (int kk = 0; kk < 4; kk++) {
                uint32_t b00, b01, b10, b11;
                LDMX4(b00, b01, b10, b11, kaddr + (uint32_t)(kk * 16) * 2u);
                mma_f16(sacc[2*jp][0], sacc[2*jp][1], sacc[2*jp][2], sacc[2*jp][3],
                        afq[kk][0], afq[kk][1], afq[kk][2], afq[kk][3], b00, b01);
                mma_f16(sacc[2*jp+1][0], sacc[2*jp+1][1], sacc[2*jp+1][2], sacc[2*jp+1][3],
                        afq[kk][0], afq[kk][1], afq[kk][2], afq[kk][3], b10, b11);
            }
        }

        if (!allone) {
            #pragma unroll
            for (int j = 0; j < 8; j++) {
                int col = j * 8 + 2 * c4;
                int mk0 = mb[col], mk1 = mb[col + 1];
                if (!mk0) { sacc[j][0] = -1e9f; sacc[j][2] = -1e9f; }
                if (!mk1) { sacc[j][1] = -1e9f; sacc[j][3] = -1e9f; }
            }
        }

        float rmax0 = -1e30f, rmax1 = -1e30f;
        #pragma unroll
        for (int j = 0; j < 8; j++) {
            rmax0 = fmaxf(rmax0, fmaxf(sacc[j][0], sacc[j][1]));
            rmax1 = fmaxf(rmax1, fmaxf(sacc[j][2], sacc[j][3]));
        }
        rmax0 = fmaxf(rmax0, __shfl_xor_sync(0xffffffffu, rmax0, 1));
        rmax0 = fmaxf(rmax0, __shfl_xor_sync(0xffffffffu, rmax0, 2));
        rmax1 = fmaxf(rmax1, __shfl_xor_sync(0xffffffffu, rmax1, 1));
        rmax1 = fmaxf(rmax1, __shfl_xor_sync(0xffffffffu, rmax1, 2));

        float mnew0 = fmaxf(m0, rmax0), mnew1 = fmaxf(m1, rmax1);
        float sc0 = ex2(m0 - mnew0), sc1 = ex2(m1 - mnew1);

        float rsum0 = 0.f, rsum1 = 0.f;
        uint32_t ap[4][4];
        #pragma unroll
        for (int j = 0; j < 8; j++) {
            float p0 = ex2(sacc[j][0] - mnew0);
            float p1 = ex2(sacc[j][1] - mnew0);
            float p2 = ex2(sacc[j][2] - mnew1);
            float p3 = ex2(sacc[j][3] - mnew1);
            rsum0 += p0 + p1; rsum1 += p2 + p3;
            int kk = j >> 1, hi = j & 1;
            ap[kk][hi ? 2 : 0] = h2u(__floats2half2_rn(p0, p1));
            ap[kk][hi ? 3 : 1] = h2u(__floats2half2_rn(p2, p3));
        }
        rsum0 += __shfl_xor_sync(0xffffffffu, rsum0, 1);
        rsum0 += __shfl_xor_sync(0xffffffffu, rsum0, 2);
        rsum1 += __shfl_xor_sync(0xffffffffu, rsum1, 1);
        rsum1 += __shfl_xor_sync(0xffffffffu, rsum1, 2);

        l0 = l0 * sc0 + rsum0; m0 = mnew0;
        l1 = l1 * sc1 + rsum1; m1 = mnew1;
        #pragma unroll
        for (int j = 0; j < 8; j++) {
            oacc[j][0] *= sc0; oacc[j][1] *= sc0;
            oacc[j][2] *= sc1; oacc[j][3] *= sc1;
        }

        #pragma unroll
        for (int dp = 0; dp < 4; dp++) {
            uint32_t vaddr = vb + (uint32_t)(dp * 16) * 2u;
            #pragma unroll
            for (int kk = 0; kk < 4; kk++) {
                uint32_t b00, b01, b10, b11;
                LDMX4T(b00, b01, b10, b11, vaddr + (uint32_t)(kk * 16 * VP) * 2u);
                mma_f16(oacc[2*dp][0], oacc[2*dp][1], oacc[2*dp][2], oacc[2*dp][3],
                        ap[kk][0], ap[kk][1], ap[kk][2], ap[kk][3], b00, b01);
                mma_f16(oacc[2*dp+1][0], oacc[2*dp+1][1], oacc[2*dp+1][2], oacc[2*dp+1][3],
                        ap[kk][0], ap[kk][1], ap[kk][2], ap[kk][3], b10, b11);
            }
        }
    }

    float inv0 = 1.0f / l0, inv1 = 1.0f / l1;
    __half* op = ctx + (size_t)(b * SEQ + qbase + wq) * D_MODEL + h * DK;
    #pragma unroll
    for (int j = 0; j < 8; j++) {
        int col = j * 8 + 2 * c4;
        *(__half2*)&op[(size_t)(r4    ) * D_MODEL + col] =
            __floats2half2_rn(oacc[j][0] * inv0, oacc[j][1] * inv0);
        *(__half2*)&op[(size_t)(r4 + 8) * D_MODEL + col] =
            __floats2half2_rn(oacc[j][2] * inv1, oacc[j][3] * inv1);
    }
}

// ---------------- launch ---------------------------------------------------
extern "C" void kernel_launch(void* const* d_in, const int* in_sizes, int n_in,
                              void* d_out, int out_size)
{
    const float* src  = (const float*)d_in[0];
    const int*   mask = (const int*)  d_in[1];
    const float* wq   = (const float*)d_in[2];
    const float* wk   = (const float*)d_in[3];
    const float* wv   = (const float*)d_in[4];
    const float* wo   = (const float*)d_in[5];
    const float* w1   = (const float*)d_in[6];
    const float* b1   = (const float*)d_in[7];
    const float* w2   = (const float*)d_in[8];
    const float* b2   = (const float*)d_in[9];
    const float* a1   = (const float*)d_in[10];
    const float* be1  = (const float*)d_in[11];
    const float* a2   = (const float*)d_in[12];
    const float* be2  = (const float*)d_in[13];
    float* out = (float*)d_out;

    __half *xln, *qb, *kb, *vb, *ctx, *x2, *ffh;
    __half *pwq, *pwk, *pwv, *pwo, *pw1, *pw2;
    float *out1;
    cudaGetSymbolAddress((void**)&xln,  h_xln);
    cudaGetSymbolAddress((void**)&qb,   h_q);
    cudaGetSymbolAddress((void**)&kb,   h_k);
    cudaGetSymbolAddress((void**)&vb,   h_v);
    cudaGetSymbolAddress((void**)&ctx,  h_ctx);
    cudaGetSymbolAddress((void**)&x2,   h_x2);
    cudaGetSymbolAddress((void**)&ffh,  h_ffh);
    cudaGetSymbolAddress((void**)&out1, g_out1);
    cudaGetSymbolAddress((void**)&pwq,  h_wq);
    cudaGetSymbolAddress((void**)&pwk,  h_wk);
    cudaGetSymbolAddress((void**)&pwv,  h_wv);
    cudaGetSymbolAddress((void**)&pwo,  h_wo);
    cudaGetSymbolAddress((void**)&pw1,  h_w1);
    cudaGetSymbolAddress((void**)&pw2,  h_w2);

    int gsm = GEMM_SMEM;
    cudaFuncSetAttribute(hgemm<0>, cudaFuncAttributeMaxDynamicSharedMemorySize, gsm);
    cudaFuncSetAttribute(hgemm<1>, cudaFuncAttributeMaxDynamicSharedMemorySize, gsm);
    cudaFuncSetAttribute(hgemm<2>, cudaFuncAttributeMaxDynamicSharedMemorySize, gsm);
    cudaFuncSetAttribute(hgemm<3>, cudaFuncAttributeMaxDynamicSharedMemorySize, gsm);
    cudaFuncSetAttribute(attn_mma, cudaFuncAttributeMaxDynamicSharedMemorySize, ATTN_SMEM);

    // 0+1) fused: weights -> fp16  ||  LN1 -> half
    prep_kernel<<<FUSED_BLOCKS, 256>>>(
        src, xln, a1, be1,
        (const float4*)wq, (const float4*)wk, (const float4*)wv, (const float4*)wo,
        (const float4*)w1, (const float4*)w2);

    // 2) QKV projections (half out; Q scaled by 0.125*log2e)
    hgemm<0><<<dim3(D_MODEL/GBN, MROWS/GBM, 3), 256, gsm>>>(
        xln, pwq, pwk, pwv, qb, kb, vb, nullptr, nullptr, MROWS, D_MODEL, D_MODEL);

    // 3) flash attention
    attn_mma<<<dim3(SEQ/BQ, NH, BATCH), 256, ATTN_SMEM>>>(qb, kb, vb, mask, ctx);

    // 4) O projection + residual (float out)
    hgemm<3><<<dim3(D_MODEL/GBN, MROWS/GBM, 1), 256, gsm>>>(
        ctx, pwo, pwo, pwo, out1, out1, out1, nullptr, src, MROWS, D_MODEL, D_MODEL);

    // 5) LN2 -> half
    ln_kernel<<<MROWS, 256>>>(out1, x2, a2, be2);

    // 6) FFN up (half out)
    hgemm<1><<<dim3(DFF/GBN, MROWS/GBM, 1), 256, gsm>>>(
        x2, pw1, pw1, pw1, ffh, ffh, ffh, b1, nullptr, MROWS, DFF, D_MODEL);

    // 7) FFN down + residual (float out)
    hgemm<2><<<dim3(D_MODEL/GBN, MROWS/GBM, 1), 256, gsm>>>(
        ffh, pw2, pw2, pw2, out, out, out, b2, out1, MROWS, D_MODEL, DFF);
}

// round 15
// speedup vs baseline: 1.5208x; 1.5208x over previous
#include <cuda_runtime.h>
#include <cuda_fp16.h>
#include <math.h>
#include <stdint.h>

#define D_MODEL 1024
#define NH      16
#define DK      64
#define DFF     4096
#define BATCH   2
#define SEQ     2048
#define MROWS   (BATCH*SEQ)   // 4096

// ---------------- scratch (device globals; no allocation allowed) ----------
__device__ __half h_xln[MROWS*D_MODEL];
__device__ __half h_q  [MROWS*D_MODEL];
__device__ __half h_k  [MROWS*D_MODEL];
__device__ __half h_v  [MROWS*D_MODEL];
__device__ __half h_ctx[MROWS*D_MODEL];
__device__ __half h_x2 [MROWS*D_MODEL];
__device__ __half h_ffh[MROWS*DFF];
__device__ float  g_out1[MROWS*D_MODEL];
// fp16 weights
__device__ __half h_wq[D_MODEL*D_MODEL];
__device__ __half h_wk[D_MODEL*D_MODEL];
__device__ __half h_wv[D_MODEL*D_MODEL];
__device__ __half h_wo[D_MODEL*D_MODEL];
__device__ __half h_w1[DFF*D_MODEL];
__device__ __half h_w2[D_MODEL*DFF];

// ---------------- helpers --------------------------------------------------
static __device__ __forceinline__ uint32_t smem_u32(const void* p) {
    uint32_t a;
    asm("{ .reg .u64 t; cvta.to.shared.u64 t, %1; cvt.u32.u64 %0, t; }"
        : "=r"(a) : "l"(p));
    return a;
}

static __device__ __forceinline__ uint32_t h2u(__half2 h) {
    union { __half2 h; uint32_t u; } x; x.h = h; return x.u;
}

static __device__ __forceinline__ float ex2(float x) {
    float y;
    asm("ex2.approx.ftz.f32 %0, %1;" : "=f"(y) : "f"(x));
    return y;
}

static __device__ __forceinline__ void mma_f16(
    float& c0, float& c1, float& c2, float& c3,
    uint32_t a0, uint32_t a1, uint32_t a2, uint32_t a3,
    uint32_t b0, uint32_t b1)
{
    asm volatile(
        "mma.sync.aligned.m16n8k16.row.col.f32.f16.f16.f32 "
        "{%0,%1,%2,%3}, {%4,%5,%6,%7}, {%8,%9}, {%0,%1,%2,%3};"
        : "+f"(c0), "+f"(c1), "+f"(c2), "+f"(c3)
        : "r"(a0), "r"(a1), "r"(a2), "r"(a3), "r"(b0), "r"(b1));
}

#define LDMX4(r0,r1,r2,r3,a) \
    asm volatile("ldmatrix.sync.aligned.m8n8.x4.shared.b16 {%0,%1,%2,%3}, [%4];" \
        : "=r"(r0),"=r"(r1),"=r"(r2),"=r"(r3) : "r"(a))
#define LDMX4T(r0,r1,r2,r3,a) \
    asm volatile("ldmatrix.sync.aligned.m8n8.x4.trans.shared.b16 {%0,%1,%2,%3}, [%4];" \
        : "=r"(r0),"=r"(r1),"=r"(r2),"=r"(r3) : "r"(a))

#define CP_ASYNC16(dst, src) \
    asm volatile("cp.async.cg.shared.global [%0], [%1], 16;" :: "r"(dst), "l"(src))

// 0.125 * log2(e): folded into Q so softmax is a bare ex2
#define QSCALE 0.18033688011112042f

// ---------------- weight conversion fp32 -> fp16 ---------------------------
#define WSEG  (D_MODEL*D_MODEL/4)
#define WBIG  (DFF*D_MODEL/4)
#define WTOT  (4*WSEG + 2*WBIG)

__global__ void round_weights(
    const float4* __restrict__ wq, const float4* __restrict__ wk,
    const float4* __restrict__ wv, const float4* __restrict__ wo,
    const float4* __restrict__ w1, const float4* __restrict__ w2)
{
    for (int i = blockIdx.x * blockDim.x + threadIdx.x; i < WTOT;
         i += gridDim.x * blockDim.x) {
        const float4* s; __half* d; int off;
        if      (i < 1*WSEG) { s = wq; d = h_wq; off = i; }
        else if (i < 2*WSEG) { s = wk; d = h_wk; off = i - 1*WSEG; }
        else if (i < 3*WSEG) { s = wv; d = h_wv; off = i - 2*WSEG; }
        else if (i < 4*WSEG) { s = wo; d = h_wo; off = i - 3*WSEG; }
        else if (i < 4*WSEG + WBIG) { s = w1; d = h_w1; off = i - 4*WSEG; }
        else                 { s = w2; d = h_w2; off = i - 4*WSEG - WBIG; }
        float4 v = s[off];
        *(__half2*)(d + 4*off)     = __floats2half2_rn(v.x, v.y);
        *(__half2*)(d + 4*off + 2) = __floats2half2_rn(v.z, v.w);
    }
}

// ======================= Tensor-core FP16 GEMM ============================
// C[M,N] = A[M,K] * B[N,K]^T; CTA 128x128x32; 8 warps 2x4 (warp 64x32);
// 3-stage cp.async; ldmatrix fragments; 2 CTAs/SM. (R12 measured-best.)
#define GBM 128
#define GBN 128
#define GBK 32
#define HP 40
#define A_HALVES (GBM*HP)
#define B_HALVES (GBN*HP)
#define STG_HALVES (A_HALVES + B_HALVES)         // 10240
#define NSTAGE 3
#define GEMM_SMEM (NSTAGE*STG_HALVES*2)          // 61440 B

// EPI: 0 = half store (*QSCALE when z==0), 1 = bias+relu half,
//      2 = bias+residual float, 3 = residual float
template<int EPI>
__global__ void __launch_bounds__(256, 2) hgemm(
    const __half* __restrict__ A,
    const __half* __restrict__ B0, const __half* __restrict__ B1, const __half* __restrict__ B2,
    void* __restrict__ C0, void* __restrict__ C1, void* __restrict__ C2,
    const float* __restrict__ bias, const float* __restrict__ res,
    int M, int N, int K)
{
    extern __shared__ __half smh[];
    uint32_t sbase = smem_u32(smh);

    const __half* Bm = B0; void* Cm = C0;
    if (blockIdx.z == 1) { Bm = B1; Cm = C1; }
    else if (blockIdx.z == 2) { Bm = B2; Cm = C2; }

    int tid  = threadIdx.x;
    int lane = tid & 31, wid = tid >> 5;
    int warp_m = (wid >> 2) * 64;      // 0 / 64
    int warp_n = (wid & 3) * 32;       // 0,32,64,96
    int rowBase = blockIdx.y * GBM;
    int colBase = blockIdx.x * GBN;
    int r4 = lane >> 2, c4 = lane & 3;
    int lg = lane >> 3, li = lane & 7;

    uint32_t aLm = (uint32_t)(((lg & 1) * 8 + li) * HP + (lg >> 1) * 8) * 2u;
    uint32_t bLm = (uint32_t)(((lg >> 1) * 8 + li) * HP + (lg & 1) * 8) * 2u;

    const __half* Ag[2]; uint32_t aOff[2];
    #pragma unroll
    for (int j = 0; j < 2; j++) {
        int slot = tid + 256 * j;
        int r = slot >> 2, c = (slot & 3) * 8;
        Ag[j] = A + (size_t)(rowBase + r) * K + c;
        aOff[j] = (uint32_t)(r * HP + c) * 2u;
    }
    const __half* Bg[2]; uint32_t bOff[2];
    #pragma unroll
    for (int j = 0; j < 2; j++) {
        int slot = tid + 256 * j;
        int r = slot >> 2, c = (slot & 3) * 8;
        Bg[j] = Bm + (size_t)(colBase + r) * K + c;
        bOff[j] = (uint32_t)(r * HP + c) * 2u;
    }

    auto issue_tile = [&](int tt, int stage) {
        int k0 = tt * GBK;
        uint32_t sA = sbase + (uint32_t)stage * (STG_HALVES * 2u);
        uint32_t sB = sA + A_HALVES * 2u;
        #pragma unroll
        for (int j = 0; j < 2; j++) CP_ASYNC16(sA + aOff[j], Ag[j] + k0);
        #pragma unroll
        for (int j = 0; j < 2; j++) CP_ASYNC16(sB + bOff[j], Bg[j] + k0);
    };

    float acc[4][4][4];
    #pragma unroll
    for (int i = 0; i < 4; i++)
        #pragma unroll
        for (int j = 0; j < 4; j++)
            #pragma unroll
            for (int e = 0; e < 4; e++) acc[i][j][e] = 0.f;

    int T = K / GBK;
    issue_tile(0, 0);
    asm volatile("cp.async.commit_group;");
    issue_tile(1, 1);
    asm volatile("cp.async.commit_group;");

    int st_c = 0, st_l = 2;
    for (int t = 0; t < T; t++) {
        asm volatile("cp.async.wait_group 1;");
        __syncthreads();

        int nt = t + 2;
        int tt = (nt >= T) ? nt - T : nt;
        issue_tile(tt, st_l);
        asm volatile("cp.async.commit_group;");
        st_l = (st_l == 2) ? 0 : st_l + 1;

        uint32_t sA = sbase + (uint32_t)st_c * (STG_HALVES * 2u);
        uint32_t sB = sA + A_HALVES * 2u;
        st_c = (st_c == 2) ? 0 : st_c + 1;

        uint32_t aBase = sA + aLm + (uint32_t)(warp_m * HP) * 2u;
        uint32_t bBase = sB + bLm + (uint32_t)(warp_n * HP) * 2u;

        #pragma unroll
        for (int kk = 0; kk < 2; kk++) {
            uint32_t kByte = (uint32_t)(kk * 16) * 2u;
            uint32_t af[4][4], bf[4][2];
            #pragma unroll
            for (int i = 0; i < 4; i++)
                LDMX4(af[i][0], af[i][1], af[i][2], af[i][3],
                      aBase + (uint32_t)(i * 16 * HP) * 2u + kByte);
            #pragma unroll
            for (int jp = 0; jp < 2; jp++)
                LDMX4(bf[2*jp][0], bf[2*jp][1], bf[2*jp+1][0], bf[2*jp+1][1],
                      bBase + (uint32_t)(jp * 16 * HP) * 2u + kByte);
            #pragma unroll
            for (int i = 0; i < 4; i++)
                #pragma unroll
                for (int j = 0; j < 4; j++)
                    mma_f16(acc[i][j][0], acc[i][j][1], acc[i][j][2], acc[i][j][3],
                            af[i][0], af[i][1], af[i][2], af[i][3],
                            bf[j][0], bf[j][1]);
        }
    }

    float qs = 1.0f;
    if (EPI == 0 && blockIdx.z == 0) qs = QSCALE;

    #pragma unroll
    for (int i = 0; i < 4; i++) {
        int row = rowBase + warp_m + i * 16 + r4;
        #pragma unroll
        for (int j = 0; j < 4; j++) {
            int col = colBase + warp_n + j * 8 + c4 * 2;
            float2 lo = make_float2(acc[i][j][0], acc[i][j][1]);
            float2 hi = make_float2(acc[i][j][2], acc[i][j][3]);
            if (EPI == 0) {
                __half* Ch = (__half*)Cm;
                *(__half2*)&Ch[(size_t)row * N + col] =
                    __floats2half2_rn(lo.x * qs, lo.y * qs);
                *(__half2*)&Ch[(size_t)(row + 8) * N + col] =
                    __floats2half2_rn(hi.x * qs, hi.y * qs);
            } else if (EPI == 1) {
                float2 bi = *(const float2*)&bias[col];
                __half* Ch = (__half*)Cm;
                *(__half2*)&Ch[(size_t)row * N + col] =
                    __floats2half2_rn(fmaxf(lo.x + bi.x, 0.f), fmaxf(lo.y + bi.y, 0.f));
                *(__half2*)&Ch[(size_t)(row + 8) * N + col] =
                    __floats2half2_rn(fmaxf(hi.x + bi.x, 0.f), fmaxf(hi.y + bi.y, 0.f));
            } else if (EPI == 2) {
                float2 bi = *(const float2*)&bias[col];
                float2 r0 = *(const float2*)&res[(size_t)row * N + col];
                float2 r1 = *(const float2*)&res[(size_t)(row + 8) * N + col];
                float* Cf = (float*)Cm;
                *(float2*)&Cf[(size_t)row * N + col] =
                    make_float2(lo.x + bi.x + r0.x, lo.y + bi.y + r0.y);
                *(float2*)&Cf[(size_t)(row + 8) * N + col] =
                    make_float2(hi.x + bi.x + r1.x, hi.y + bi.y + r1.y);
            } else {
                float2 r0 = *(const float2*)&res[(size_t)row * N + col];
                float2 r1 = *(const float2*)&res[(size_t)(row + 8) * N + col];
                float* Cf = (float*)Cm;
                *(float2*)&Cf[(size_t)row * N + col]       = make_float2(lo.x + r0.x, lo.y + r0.y);
                *(float2*)&Cf[(size_t)(row + 8) * N + col] = make_float2(hi.x + r1.x, hi.y + r1.y);
            }
        }
    }
}

// ---------------- LayerNorm (torch: ddof=1, eps added to std) --------------
__global__ void __launch_bounds__(256) ln_kernel(
    const float* __restrict__ x, __half* __restrict__ y,
    const float* __restrict__ alpha, const float* __restrict__ beta)
{
    int row = blockIdx.x;
    const float4* xr = (const float4*)(x + (size_t)row * D_MODEL);
    float4 v = xr[threadIdx.x];
    float s  = v.x + v.y + v.z + v.w;
    float sq = v.x*v.x + v.y*v.y + v.z*v.z + v.w*v.w;

    __shared__ float red[18];
    #pragma unroll
    for (int o = 16; o; o >>= 1) {
        s  += __shfl_xor_sync(0xffffffffu, s,  o);
        sq += __shfl_xor_sync(0xffffffffu, sq, o);
    }
    int w = threadIdx.x >> 5;
    if ((threadIdx.x & 31) == 0) { red[w] = s; red[8 + w] = sq; }
    __syncthreads();
    if (threadIdx.x == 0) {
        float ts = 0.f, tq = 0.f;
        #pragma unroll
        for (int i = 0; i < 8; i++) { ts += red[i]; tq += red[8 + i]; }
        red[16] = ts; red[17] = tq;
    }
    __syncthreads();
    float ts = red[16], tq = red[17];

    float mean = ts * (1.0f / D_MODEL);
    float var  = (tq - ts * mean) * (1.0f / (D_MODEL - 1));
    var = fmaxf(var, 0.0f);
    float denom = sqrtf(var) + 1e-6f;
    float a  = alpha[0], be = beta[0];
    float r  = a / denom;

    __half* yr = y + (size_t)row * D_MODEL + threadIdx.x * 4;
    *(__half2*)(yr)     = __floats2half2_rn((v.x - mean) * r + be, (v.y - mean) * r + be);
    *(__half2*)(yr + 2) = __floats2half2_rn((v.z - mean) * r + be, (v.w - mean) * r + be);
}

// ============== Flash attention, fp16 mma + ldmatrix ======================
// 4-stage KV ring, single barrier per tile; Q pre-scaled; bare ex2 softmax.
// (R12 measured-best configuration.)
#define BQ  128
#define BKV 64
#define NKV 4
#define QP  72
#define KP  72
#define VP  72
#define ATTN_SMEM ((BQ*QP + NKV*BKV*KP + NKV*BKV*VP)*2 + NKV*64*4 + 8*4)

__global__ void __launch_bounds__(256, 2) attn_mma(
    const __half* __restrict__ q, const __half* __restrict__ k,
    const __half* __restrict__ v, const int* __restrict__ mask,
    __half* __restrict__ ctx)
{
    extern __shared__ __half sa[];
    __half* Qs = sa;                       // [128][72]
    __half* Ks = Qs + BQ*QP;               // NKV x [64][72]
    __half* Vs = Ks + NKV*BKV*KP;          // NKV x [64][72]
    int*    ms = (int*)(Vs + NKV*BKV*VP);  // NKV x [64]
    int*    fl = ms + NKV*64;              // 2 flags per stage

    int tid = threadIdx.x, lane = tid & 31, wid = tid >> 5;
    int r4 = lane >> 2, c4 = lane & 3;
    int lg = lane >> 3, li = lane & 7;
    int qt = blockIdx.x, h = blockIdx.y, b = blockIdx.z;
    int qbase = qt * BQ;
    int wq = wid * 16;

    const __half* qp = q + (size_t)(b * SEQ) * D_MODEL + h * DK;
    const __half* kp = k + (size_t)(b * SEQ) * D_MODEL + h * DK;
    const __half* vp = v + (size_t)(b * SEQ) * D_MODEL + h * DK;
    const int* maskb = mask + b * SEQ;

    uint32_t kLm = (uint32_t)(((lg >> 1) * 8 + li) * KP + (lg & 1) * 8) * 2u;
    uint32_t vLm = (uint32_t)(((lg & 1) * 8 + li) * VP + (lg >> 1) * 8) * 2u;

    #pragma unroll
    for (int i = 0; i < 4; i++) {
        int slot = tid + i * 256;
        int r = slot >> 3, c = (slot & 7) * 8;
        *(uint4*)&Qs[r * QP + c] = *(const uint4*)(qp + (size_t)(qbase + r) * D_MODEL + c);
    }

    uint32_t ksb = smem_u32(Ks), vsb = smem_u32(Vs);
    auto issue = [&](int tt) {
        int buf = tt & (NKV - 1), kv0 = tt * BKV;
        #pragma unroll
        for (int i = 0; i < 4; i++) {
            int slot = tid + i * 256;
            int r = (slot & 511) >> 3, c = (slot & 7) * 8;
            if (slot < 512)
                CP_ASYNC16(ksb + (uint32_t)(buf*BKV*KP + r*KP + c)*2u,
                           kp + (size_t)(kv0 + r) * D_MODEL + c);
            else
                CP_ASYNC16(vsb + (uint32_t)(buf*BKV*VP + r*VP + c)*2u,
                           vp + (size_t)(kv0 + r) * D_MODEL + c);
        }
        asm volatile("cp.async.commit_group;");
    };

    issue(0);
    issue(1);
    issue(2);
    if (tid < 192) {
        int m = maskb[tid];
        ms[tid] = m;
        int all = __all_sync(0xffffffffu, m != 0);
        if ((tid & 31) == 0) fl[tid >> 5] = all;
    }
    __syncthreads();

    uint32_t afq[4][4];
    {
        const __half* qrow = Qs + wq * QP + 2 * c4;
        #pragma unroll
        for (int kk = 0; kk < 4; kk++) {
            int k16 = kk * 16;
            afq[kk][0] = h2u(*(const __half2*)(qrow + (r4    ) * QP + k16));
            afq[kk][1] = h2u(*(const __half2*)(qrow + (r4 + 8) * QP + k16));
            afq[kk][2] = h2u(*(const __half2*)(qrow + (r4    ) * QP + k16 + 8));
            afq[kk][3] = h2u(*(const __half2*)(qrow + (r4 + 8) * QP + k16 + 8));
        }
    }

    float m0 = -1e30f, m1 = -1e30f, l0 = 0.f, l1 = 0.f;
    float oacc[8][4];
    #pragma unroll
    for (int j = 0; j < 8; j++)
        #pragma unroll
        for (int e = 0; e < 4; e++) oacc[j][e] = 0.f;

    const int T = SEQ / BKV;   // 32
    for (int t = 0; t < T; t++) {
        int buf = t & (NKV - 1);
        asm volatile("cp.async.wait_group 2;");
        __syncthreads();

        if (t + 3 < T) {
            issue(t + 3);
            if (tid < 64) {
                int st = (t + 3) & (NKV - 1);
                int m = maskb[(t + 3) * BKV + tid];
                ms[st * 64 + tid] = m;
                int all = __all_sync(0xffffffffu, m != 0);
                if ((tid & 31) == 0) fl[st * 2 + (tid >> 5)] = all;
            }
        }

        uint32_t kb = ksb + (uint32_t)(buf * BKV * KP) * 2u + kLm;
        uint32_t vb = vsb + (uint32_t)(buf * BKV * VP) * 2u + vLm;
        const int* mb = ms + buf * 64;
        bool allone = fl[buf * 2] && fl[buf * 2 + 1];

        float sacc[8][4];
        #pragma unroll
        for (int j = 0; j < 8; j++)
            #pragma unroll
            for (int e = 0; e < 4; e++) sacc[j][e] = 0.f;

        #pragma unroll
        for (int jp = 0; jp < 4; jp++) {
            uint32_t kaddr = kb + (uint32_t)(jp * 16 * KP) * 2u;
            #pragma unroll
            for (int kk = 0; kk < 4; kk++) {
                uint32_t b00, b01, b10, b11;
                LDMX4(b00, b01, b10, b11, kaddr + (uint32_t)(kk * 16) * 2u);
                mma_f16(sacc[2*jp][0], sacc[2*jp][1], sacc[2*jp][2], sacc[2*jp][3],
                        afq[kk][0], afq[kk][1], afq[kk][2], afq[kk][3], b00, b01);
                mma_f16(sacc[2*jp+1][0], sacc[2*jp+1][1], sacc[2*jp+1][2], sacc[2*jp+1][3],
                        afq[kk][0], afq[kk][1], afq[kk][2], afq[kk][3], b10, b11);
            }
        }

        if (!allone) {
            #pragma unroll
            for (int j = 0; j < 8; j++) {
                int col = j * 8 + 2 * c4;
                int mk0 = mb[col], mk1 = mb[col + 1];
                if (!mk0) { sacc[j][0] = -1e9f; sacc[j][2] = -1e9f; }
                if (!mk1) { sacc[j][1] = -1e9f; sacc[j][3] = -1e9f; }
            }
        }

        float rmax0 = -1e30f, rmax1 = -1e30f;
        #pragma unroll
        for (int j = 0; j < 8; j++) {
            rmax0 = fmaxf(rmax0, fmaxf(sacc[j][0], sacc[j][1]));
            rmax1 = fmaxf(rmax1, fmaxf(sacc[j][2], sacc[j][3]));
        }
        rmax0 = fmaxf(rmax0, __shfl_xor_sync(0xffffffffu, rmax0, 1));
        rmax0 = fmaxf(rmax0, __shfl_xor_sync(0xffffffffu, rmax0, 2));
        rmax1 = fmaxf(rmax1, __shfl_xor_sync(0xffffffffu, rmax1, 1));
        rmax1 = fmaxf(rmax1, __shfl_xor_sync(0xffffffffu, rmax1, 2));

        float mnew0 = fmaxf(m0, rmax0), mnew1 = fmaxf(m1, rmax1);
        float sc0 = ex2(m0 - mnew0), sc1 = ex2(m1 - mnew1);

        float rsum0 = 0.f, rsum1 = 0.f;
        uint32_t ap[4][4];
        #pragma unroll
        for (int j = 0; j < 8; j++) {
            float p0 = ex2(sacc[j][0] - mnew0);
            float p1 = ex2(sacc[j][1] - mnew0);
            float p2 = ex2(sacc[j][2] - mnew1);
            float p3 = ex2(sacc[j][3] - mnew1);
            rsum0 += p0 + p1; rsum1 += p2 + p3;
            int kk = j >> 1, hi = j & 1;
            ap[kk][hi ? 2 : 0] = h2u(__floats2half2_rn(p0, p1));
            ap[kk][hi ? 3 : 1] = h2u(__floats2half2_rn(p2, p3));
        }
        rsum0 += __shfl_xor_sync(0xffffffffu, rsum0, 1);
        rsum0 += __shfl_xor_sync(0xffffffffu, rsum0, 2);
        rsum1 += __shfl_xor_sync(0xffffffffu, rsum1, 1);
        rsum1 += __shfl_xor_sync(0xffffffffu, rsum1, 2);

        l0 = l0 * sc0 + rsum0; m0 = mnew0;
        l1 = l1 * sc1 + rsum1; m1 = mnew1;
        #pragma unroll
        for (int j = 0; j < 8; j++) {
            oacc[j][0] *= sc0; oacc[j][1] *= sc0;
            oacc[j][2] *= sc1; oacc[j][3] *= sc1;
        }

        #pragma unroll
        for (int dp = 0; dp < 4; dp++) {
            uint32_t vaddr = vb + (uint32_t)(dp * 16) * 2u;
            #pragma unroll
            for (int kk = 0; kk < 4; kk++) {
                uint32_t b00, b01, b10, b11;
                LDMX4T(b00, b01, b10, b11, vaddr + (uint32_t)(kk * 16 * VP) * 2u);
                mma_f16(oacc[2*dp][0], oacc[2*dp][1], oacc[2*dp][2], oacc[2*dp][3],
                        ap[kk][0], ap[kk][1], ap[kk][2], ap[kk][3], b00, b01);
                mma_f16(oacc[2*dp+1][0], oacc[2*dp+1][1], oacc[2*dp+1][2], oacc[2*dp+1][3],
                        ap[kk][0], ap[kk][1], ap[kk][2], ap[kk][3], b10, b11);
            }
        }
    }

    float inv0 = 1.0f / l0, inv1 = 1.0f / l1;
    __half* op = ctx + (size_t)(b * SEQ + qbase + wq) * D_MODEL + h * DK;
    #pragma unroll
    for (int j = 0; j < 8; j++) {
        int col = j * 8 + 2 * c4;
        *(__half2*)&op[(size_t)(r4    ) * D_MODEL + col] =
            __floats2half2_rn(oacc[j][0] * inv0, oacc[j][1] * inv0);
        *(__half2*)&op[(size_t)(r4 + 8) * D_MODEL + col] =
            __floats2half2_rn(oacc[j][2] * inv1, oacc[j][3] * inv1);
    }
}

// ---------------- launch ---------------------------------------------------
extern "C" void kernel_launch(void* const* d_in, const int* in_sizes, int n_in,
                              void* d_out, int out_size)
{
    const float* src  = (const float*)d_in[0];
    const int*   mask = (const int*)  d_in[1];
    const float* wq   = (const float*)d_in[2];
    const float* wk   = (const float*)d_in[3];
    const float* wv   = (const float*)d_in[4];
    const float* wo   = (const float*)d_in[5];
    const float* w1   = (const float*)d_in[6];
    const float* b1   = (const float*)d_in[7];
    const float* w2   = (const float*)d_in[8];
    const float* b2   = (const float*)d_in[9];
    const float* a1   = (const float*)d_in[10];
    const float* be1  = (const float*)d_in[11];
    const float* a2   = (const float*)d_in[12];
    const float* be2  = (const float*)d_in[13];
    float* out = (float*)d_out;

    __half *xln, *qb, *kb, *vb, *ctx, *x2, *ffh;
    __half *pwq, *pwk, *pwv, *pwo, *pw1, *pw2;
    float *out1;
    cudaGetSymbolAddress((void**)&xln,  h_xln);
    cudaGetSymbolAddress((void**)&qb,   h_q);
    cudaGetSymbolAddress((void**)&kb,   h_k);
    cudaGetSymbolAddress((void**)&vb,   h_v);
    cudaGetSymbolAddress((void**)&ctx,  h_ctx);
    cudaGetSymbolAddress((void**)&x2,   h_x2);
    cudaGetSymbolAddress((void**)&ffh,  h_ffh);
    cudaGetSymbolAddress((void**)&out1, g_out1);
    cudaGetSymbolAddress((void**)&pwq,  h_wq);
    cudaGetSymbolAddress((void**)&pwk,  h_wk);
    cudaGetSymbolAddress((void**)&pwv,  h_wv);
    cudaGetSymbolAddress((void**)&pwo,  h_wo);
    cudaGetSymbolAddress((void**)&pw1,  h_w1);
    cudaGetSymbolAddress((void**)&pw2,  h_w2);

    int gsm = GEMM_SMEM;
    cudaFuncSetAttribute(hgemm<0>, cudaFuncAttributeMaxDynamicSharedMemorySize, gsm);
    cudaFuncSetAttribute(hgemm<1>, cudaFuncAttributeMaxDynamicSharedMemorySize, gsm);
    cudaFuncSetAttribute(hgemm<2>, cudaFuncAttributeMaxDynamicSharedMemorySize, gsm);
    cudaFuncSetAttribute(hgemm<3>, cudaFuncAttributeMaxDynamicSharedMemorySize, gsm);
    cudaFuncSetAttribute(attn_mma, cudaFuncAttributeMaxDynamicSharedMemorySize, ATTN_SMEM);

    // 0) weights -> fp16
    round_weights<<<2048, 256>>>(
        (const float4*)wq, (const float4*)wk, (const float4*)wv, (const float4*)wo,
        (const float4*)w1, (const float4*)w2);

    // 1) LN1 -> half
    ln_kernel<<<MROWS, 256>>>(src, xln, a1, be1);

    // 2) QKV projections (half out; Q scaled by 0.125*log2e)
    hgemm<0><<<dim3(D_MODEL/GBN, MROWS/GBM, 3), 256, gsm>>>(
        xln, pwq, pwk, pwv, qb, kb, vb, nullptr, nullptr, MROWS, D_MODEL, D_MODEL);

    // 3) flash attention
    attn_mma<<<dim3(SEQ/BQ, NH, BATCH), 256, ATTN_SMEM>>>(qb, kb, vb, mask, ctx);

    // 4) O projection + residual (float out)
    hgemm<3><<<dim3(D_MODEL/GBN, MROWS/GBM, 1), 256, gsm>>>(
        ctx, pwo, pwo, pwo, out1, out1, out1, nullptr, src, MROWS, D_MODEL, D_MODEL);

    // 5) LN2 -> half
    ln_kernel<<<MROWS, 256>>>(out1, x2, a2, be2);

    // 6) FFN up (half out)
    hgemm<1><<<dim3(DFF/GBN, MROWS/GBM, 1), 256, gsm>>>(
        x2, pw1, pw1, pw1, ffh, ffh, ffh, b1, nullptr, MROWS, DFF, D_MODEL);

    // 7) FFN down + residual (float out)
    hgemm<2><<<dim3(D_MODEL/GBN, MROWS/GBM, 1), 256, gsm>>>(
        ffh, pw2, pw2, pw2, out, out, out, b2, out1, MROWS, D_MODEL, DFF);
}

// round 16
// speedup vs baseline: 1.5213x; 1.0003x over previous
#include <cuda_runtime.h>
#include <cuda_fp16.h>
#include <math.h>
#include <stdint.h>

#define D_MODEL 1024
#define NH      16
#define DK      64
#define DFF     4096
#define BATCH   2
#define SEQ     2048
#define MROWS   (BATCH*SEQ)   // 4096

// ---------------- scratch (device globals; no allocation allowed) ----------
__device__ __half h_xln[MROWS*D_MODEL];
__device__ __half h_q  [MROWS*D_MODEL];
__device__ __half h_k  [MROWS*D_MODEL];
__device__ __half h_v  [MROWS*D_MODEL];
__device__ __half h_ctx[MROWS*D_MODEL];
__device__ __half h_x2 [MROWS*D_MODEL];
__device__ __half h_ffh[MROWS*DFF];
__device__ float  g_out1[MROWS*D_MODEL];
// fp16 weights
__device__ __half h_wq[D_MODEL*D_MODEL];
__device__ __half h_wk[D_MODEL*D_MODEL];
__device__ __half h_wv[D_MODEL*D_MODEL];
__device__ __half h_wo[D_MODEL*D_MODEL];
__device__ __half h_w1[DFF*D_MODEL];
__device__ __half h_w2[D_MODEL*DFF];

// ---------------- helpers --------------------------------------------------
static __device__ __forceinline__ uint32_t smem_u32(const void* p) {
    uint32_t a;
    asm("{ .reg .u64 t; cvta.to.shared.u64 t, %1; cvt.u32.u64 %0, t; }"
        : "=r"(a) : "l"(p));
    return a;
}

static __device__ __forceinline__ uint32_t h2u(__half2 h) {
    union { __half2 h; uint32_t u; } x; x.h = h; return x.u;
}

static __device__ __forceinline__ float ex2(float x) {
    float y;
    asm("ex2.approx.ftz.f32 %0, %1;" : "=f"(y) : "f"(x));
    return y;
}

static __device__ __forceinline__ void mma_f16(
    float& c0, float& c1, float& c2, float& c3,
    uint32_t a0, uint32_t a1, uint32_t a2, uint32_t a3,
    uint32_t b0, uint32_t b1)
{
    asm volatile(
        "mma.sync.aligned.m16n8k16.row.col.f32.f16.f16.f32 "
        "{%0,%1,%2,%3}, {%4,%5,%6,%7}, {%8,%9}, {%0,%1,%2,%3};"
        : "+f"(c0), "+f"(c1), "+f"(c2), "+f"(c3)
        : "r"(a0), "r"(a1), "r"(a2), "r"(a3), "r"(b0), "r"(b1));
}

#define LDMX4(r0,r1,r2,r3,a) \
    asm volatile("ldmatrix.sync.aligned.m8n8.x4.shared.b16 {%0,%1,%2,%3}, [%4];" \
        : "=r"(r0),"=r"(r1),"=r"(r2),"=r"(r3) : "r"(a))
#define LDMX4T(r0,r1,r2,r3,a) \
    asm volatile("ldmatrix.sync.aligned.m8n8.x4.trans.shared.b16 {%0,%1,%2,%3}, [%4];" \
        : "=r"(r0),"=r"(r1),"=r"(r2),"=r"(r3) : "r"(a))

#define CP_ASYNC16(dst, src) \
    asm volatile("cp.async.cg.shared.global [%0], [%1], 16;" :: "r"(dst), "l"(src))

// 0.125 * log2(e): folded into Q so softmax is a bare ex2
#define QSCALE 0.18033688011112042f

// ---------------- weight conversion fp32 -> fp16 ---------------------------
#define WSEG  (D_MODEL*D_MODEL/4)
#define WBIG  (DFF*D_MODEL/4)
#define WTOT  (4*WSEG + 2*WBIG)

__global__ void round_weights(
    const float4* __restrict__ wq, const float4* __restrict__ wk,
    const float4* __restrict__ wv, const float4* __restrict__ wo,
    const float4* __restrict__ w1, const float4* __restrict__ w2)
{
    for (int i = blockIdx.x * blockDim.x + threadIdx.x; i < WTOT;
         i += gridDim.x * blockDim.x) {
        const float4* s; __half* d; int off;
        if      (i < 1*WSEG) { s = wq; d = h_wq; off = i; }
        else if (i < 2*WSEG) { s = wk; d = h_wk; off = i - 1*WSEG; }
        else if (i < 3*WSEG) { s = wv; d = h_wv; off = i - 2*WSEG; }
        else if (i < 4*WSEG) { s = wo; d = h_wo; off = i - 3*WSEG; }
        else if (i < 4*WSEG + WBIG) { s = w1; d = h_w1; off = i - 4*WSEG; }
        else                 { s = w2; d = h_w2; off = i - 4*WSEG - WBIG; }
        float4 v = s[off];
        *(__half2*)(d + 4*off)     = __floats2half2_rn(v.x, v.y);
        *(__half2*)(d + 4*off + 2) = __floats2half2_rn(v.z, v.w);
    }
}

// ======================= Tensor-core FP16 GEMM ============================
// C[M,N] = A[M,K] * B[N,K]^T; CTA 128x128x32; 8 warps 2x4 (warp 64x32);
// 3-stage cp.async; ldmatrix fragments; 2 CTAs/SM. (R12 measured-best.)
#define GBM 128
#define GBN 128
#define GBK 32
#define HP 40
#define A_HALVES (GBM*HP)
#define B_HALVES (GBN*HP)
#define STG_HALVES (A_HALVES + B_HALVES)         // 10240
#define NSTAGE 3
#define GEMM_SMEM (NSTAGE*STG_HALVES*2)          // 61440 B

// EPI: 0 = half store (*QSCALE when z==0), 1 = bias+relu half,
//      2 = bias+residual float, 3 = residual float
template<int EPI>
__global__ void __launch_bounds__(256, 2) hgemm(
    const __half* __restrict__ A,
    const __half* __restrict__ B0, const __half* __restrict__ B1, const __half* __restrict__ B2,
    void* __restrict__ C0, void* __restrict__ C1, void* __restrict__ C2,
    const float* __restrict__ bias, const float* __restrict__ res,
    int M, int N, int K)
{
    extern __shared__ __half smh[];
    uint32_t sbase = smem_u32(smh);

    const __half* Bm = B0; void* Cm = C0;
    if (blockIdx.z == 1) { Bm = B1; Cm = C1; }
    else if (blockIdx.z == 2) { Bm = B2; Cm = C2; }

    int tid  = threadIdx.x;
    int lane = tid & 31, wid = tid >> 5;
    int warp_m = (wid >> 2) * 64;      // 0 / 64
    int warp_n = (wid & 3) * 32;       // 0,32,64,96
    int rowBase = blockIdx.y * GBM;
    int colBase = blockIdx.x * GBN;
    int r4 = lane >> 2, c4 = lane & 3;
    int lg = lane >> 3, li = lane & 7;

    uint32_t aLm = (uint32_t)(((lg & 1) * 8 + li) * HP + (lg >> 1) * 8) * 2u;
    uint32_t bLm = (uint32_t)(((lg >> 1) * 8 + li) * HP + (lg & 1) * 8) * 2u;

    const __half* Ag[2]; uint32_t aOff[2];
    #pragma unroll
    for (int j = 0; j < 2; j++) {
        int slot = tid + 256 * j;
        int r = slot >> 2, c = (slot & 3) * 8;
        Ag[j] = A + (size_t)(rowBase + r) * K + c;
        aOff[j] = (uint32_t)(r * HP + c) * 2u;
    }
    const __half* Bg[2]; uint32_t bOff[2];
    #pragma unroll
    for (int j = 0; j < 2; j++) {
        int slot = tid + 256 * j;
        int r = slot >> 2, c = (slot & 3) * 8;
        Bg[j] = Bm + (size_t)(colBase + r) * K + c;
        bOff[j] = (uint32_t)(r * HP + c) * 2u;
    }

    auto issue_tile = [&](int tt, int stage) {
        int k0 = tt * GBK;
        uint32_t sA = sbase + (uint32_t)stage * (STG_HALVES * 2u);
        uint32_t sB = sA + A_HALVES * 2u;
        #pragma unroll
        for (int j = 0; j < 2; j++) CP_ASYNC16(sA + aOff[j], Ag[j] + k0);
        #pragma unroll
        for (int j = 0; j < 2; j++) CP_ASYNC16(sB + bOff[j], Bg[j] + k0);
    };

    float acc[4][4][4];
    #pragma unroll
    for (int i = 0; i < 4; i++)
        #pragma unroll
        for (int j = 0; j < 4; j++)
            #pragma unroll
            for (int e = 0; e < 4; e++) acc[i][j][e] = 0.f;

    int T = K / GBK;
    issue_tile(0, 0);
    asm volatile("cp.async.commit_group;");
    issue_tile(1, 1);
    asm volatile("cp.async.commit_group;");

    int st_c = 0, st_l = 2;
    for (int t = 0; t < T; t++) {
        asm volatile("cp.async.wait_group 1;");
        __syncthreads();

        int nt = t + 2;
        int tt = (nt >= T) ? nt - T : nt;
        issue_tile(tt, st_l);
        asm volatile("cp.async.commit_group;");
        st_l = (st_l == 2) ? 0 : st_l + 1;

        uint32_t sA = sbase + (uint32_t)st_c * (STG_HALVES * 2u);
        uint32_t sB = sA + A_HALVES * 2u;
        st_c = (st_c == 2) ? 0 : st_c + 1;

        uint32_t aBase = sA + aLm + (uint32_t)(warp_m * HP) * 2u;
        uint32_t bBase = sB + bLm + (uint32_t)(warp_n * HP) * 2u;

        #pragma unroll
        for (int kk = 0; kk < 2; kk++) {
            uint32_t kByte = (uint32_t)(kk * 16) * 2u;
            uint32_t af[4][4], bf[4][2];
            #pragma unroll
            for (int i = 0; i < 4; i++)
                LDMX4(af[i][0], af[i][1], af[i][2], af[i][3],
                      aBase + (uint32_t)(i * 16 * HP) * 2u + kByte);
            #pragma unroll
            for (int jp = 0; jp < 2; jp++)
                LDMX4(bf[2*jp][0], bf[2*jp][1], bf[2*jp+1][0], bf[2*jp+1][1],
                      bBase + (uint32_t)(jp * 16 * HP) * 2u + kByte);
            #pragma unroll
            for (int i = 0; i < 4; i++)
                #pragma unroll
                for (int j = 0; j < 4; j++)
                    mma_f16(acc[i][j][0], acc[i][j][1], acc[i][j][2], acc[i][j][3],
                            af[i][0], af[i][1], af[i][2], af[i][3],
                            bf[j][0], bf[j][1]);
        }
    }

    float qs = 1.0f;
    if (EPI == 0 && blockIdx.z == 0) qs = QSCALE;

    #pragma unroll
    for (int i = 0; i < 4; i++) {
        int row = rowBase + warp_m + i * 16 + r4;
        #pragma unroll
        for (int j = 0; j < 4; j++) {
            int col = colBase + warp_n + j * 8 + c4 * 2;
            float2 lo = make_float2(acc[i][j][0], acc[i][j][1]);
            float2 hi = make_float2(acc[i][j][2], acc[i][j][3]);
            if (EPI == 0) {
                __half* Ch = (__half*)Cm;
                *(__half2*)&Ch[(size_t)row * N + col] =
                    __floats2half2_rn(lo.x * qs, lo.y * qs);
                *(__half2*)&Ch[(size_t)(row + 8) * N + col] =
                    __floats2half2_rn(hi.x * qs, hi.y * qs);
            } else if (EPI == 1) {
                float2 bi = *(const float2*)&bias[col];
                __half* Ch = (__half*)Cm;
                *(__half2*)&Ch[(size_t)row * N + col] =
                    __floats2half2_rn(fmaxf(lo.x + bi.x, 0.f), fmaxf(lo.y + bi.y, 0.f));
                *(__half2*)&Ch[(size_t)(row + 8) * N + col] =
                    __floats2half2_rn(fmaxf(hi.x + bi.x, 0.f), fmaxf(hi.y + bi.y, 0.f));
            } else if (EPI == 2) {
                float2 bi = *(const float2*)&bias[col];
                float2 r0 = *(const float2*)&res[(size_t)row * N + col];
                float2 r1 = *(const float2*)&res[(size_t)(row + 8) * N + col];
                float* Cf = (float*)Cm;
                *(float2*)&Cf[(size_t)row * N + col] =
                    make_float2(lo.x + bi.x + r0.x, lo.y + bi.y + r0.y);
                *(float2*)&Cf[(size_t)(row + 8) * N + col] =
                    make_float2(hi.x + bi.x + r1.x, hi.y + bi.y + r1.y);
            } else {
                float2 r0 = *(const float2*)&res[(size_t)row * N + col];
                float2 r1 = *(const float2*)&res[(size_t)(row + 8) * N + col];
                float* Cf = (float*)Cm;
                *(float2*)&Cf[(size_t)row * N + col]       = make_float2(lo.x + r0.x, lo.y + r0.y);
                *(float2*)&Cf[(size_t)(row + 8) * N + col] = make_float2(hi.x + r1.x, hi.y + r1.y);
            }
        }
    }
}

// ---------------- LayerNorm (torch: ddof=1, eps added to std) --------------
__global__ void __launch_bounds__(256) ln_kernel(
    const float* __restrict__ x, __half* __restrict__ y,
    const float* __restrict__ alpha, const float* __restrict__ beta)
{
    int row = blockIdx.x;
    const float4* xr = (const float4*)(x + (size_t)row * D_MODEL);
    float4 v = xr[threadIdx.x];
    float s  = v.x + v.y + v.z + v.w;
    float sq = v.x*v.x + v.y*v.y + v.z*v.z + v.w*v.w;

    __shared__ float red[18];
    #pragma unroll
    for (int o = 16; o; o >>= 1) {
        s  += __shfl_xor_sync(0xffffffffu, s,  o);
        sq += __shfl_xor_sync(0xffffffffu, sq, o);
    }
    int w = threadIdx.x >> 5;
    if ((threadIdx.x & 31) == 0) { red[w] = s; red[8 + w] = sq; }
    __syncthreads();
    if (threadIdx.x == 0) {
        float ts = 0.f, tq = 0.f;
        #pragma unroll
        for (int i = 0; i < 8; i++) { ts += red[i]; tq += red[8 + i]; }
        red[16] = ts; red[17] = tq;
    }
    __syncthreads();
    float ts = red[16], tq = red[17];

    float mean = ts * (1.0f / D_MODEL);
    float var  = (tq - ts * mean) * (1.0f / (D_MODEL - 1));
    var = fmaxf(var, 0.0f);
    float denom = sqrtf(var) + 1e-6f;
    float a  = alpha[0], be = beta[0];
    float r  = a / denom;

    __half* yr = y + (size_t)row * D_MODEL + threadIdx.x * 4;
    *(__half2*)(yr)     = __floats2half2_rn((v.x - mean) * r + be, (v.y - mean) * r + be);
    *(__half2*)(yr + 2) = __floats2half2_rn((v.z - mean) * r + be, (v.w - mean) * r + be);
}

// ============== Flash attention, fp16 mma + ldmatrix ======================
// 4-stage KV ring, single barrier per tile; Q pre-scaled; bare ex2 softmax.
// MMA loops are k-outer so consecutive HMMAs hit independent accumulators.
#define BQ  128
#define BKV 64
#define NKV 4
#define QP  72
#define KP  72
#define VP  72
#define ATTN_SMEM ((BQ*QP + NKV*BKV*KP + NKV*BKV*VP)*2 + NKV*64*4 + 8*4)

__global__ void __launch_bounds__(256, 2) attn_mma(
    const __half* __restrict__ q, const __half* __restrict__ k,
    const __half* __restrict__ v, const int* __restrict__ mask,
    __half* __restrict__ ctx)
{
    extern __shared__ __half sa[];
    __half* Qs = sa;                       // [128][72]
    __half* Ks = Qs + BQ*QP;               // NKV x [64][72]
    __half* Vs = Ks + NKV*BKV*KP;          // NKV x [64][72]
    int*    ms = (int*)(Vs + NKV*BKV*VP);  // NKV x [64]
    int*    fl = ms + NKV*64;              // 2 flags per stage

    int tid = threadIdx.x, lane = tid & 31, wid = tid >> 5;
    int r4 = lane >> 2, c4 = lane & 3;
    int lg = lane >> 3, li = lane & 7;
    int qt = blockIdx.x, h = blockIdx.y, b = blockIdx.z;
    int qbase = qt * BQ;
    int wq = wid * 16;

    const __half* qp = q + (size_t)(b * SEQ) * D_MODEL + h * DK;
    const __half* kp = k + (size_t)(b * SEQ) * D_MODEL + h * DK;
    const __half* vp = v + (size_t)(b * SEQ) * D_MODEL + h * DK;
    const int* maskb = mask + b * SEQ;

    uint32_t kLm = (uint32_t)(((lg >> 1) * 8 + li) * KP + (lg & 1) * 8) * 2u;
    uint32_t vLm = (uint32_t)(((lg & 1) * 8 + li) * VP + (lg >> 1) * 8) * 2u;

    #pragma unroll
    for (int i = 0; i < 4; i++) {
        int slot = tid + i * 256;
        int r = slot >> 3, c = (slot & 7) * 8;
        *(uint4*)&Qs[r * QP + c] = *(const uint4*)(qp + (size_t)(qbase + r) * D_MODEL + c);
    }

    uint32_t ksb = smem_u32(Ks), vsb = smem_u32(Vs);
    auto issue = [&](int tt) {
        int buf = tt & (NKV - 1), kv0 = tt * BKV;
        #pragma unroll
        for (int i = 0; i < 4; i++) {
            int slot = tid + i * 256;
            int r = (slot & 511) >> 3, c = (slot & 7) * 8;
            if (slot < 512)
                CP_ASYNC16(ksb + (uint32_t)(buf*BKV*KP + r*KP + c)*2u,
                           kp + (size_t)(kv0 + r) * D_MODEL + c);
            else
                CP_ASYNC16(vsb + (uint32_t)(buf*BKV*VP + r*VP + c)*2u,
                           vp + (size_t)(kv0 + r) * D_MODEL + c);
        }
        asm volatile("cp.async.commit_group;");
    };

    issue(0);
    issue(1);
    issue(2);
    if (tid < 192) {
        int m = maskb[tid];
        ms[tid] = m;
        int all = __all_sync(0xffffffffu, m != 0);
        if ((tid & 31) == 0) fl[tid >> 5] = all;
    }
    __syncthreads();

    uint32_t afq[4][4];
    {
        const __half* qrow = Qs + wq * QP + 2 * c4;
        #pragma unroll
        for (int kk = 0; kk < 4; kk++) {
            int k16 = kk * 16;
            afq[kk][0] = h2u(*(const __half2*)(qrow + (r4    ) * QP + k16));
            afq[kk][1] = h2u(*(const __half2*)(qrow + (r4 + 8) * QP + k16));
            afq[kk][2] = h2u(*(const __half2*)(qrow + (r4    ) * QP + k16 + 8));
            afq[kk][3] = h2u(*(const __half2*)(qrow + (r4 + 8) * QP + k16 + 8));
        }
    }

    float m0 = -1e30f, m1 = -1e30f, l0 = 0.f, l1 = 0.f;
    float oacc[8][4];
    #pragma unroll
    for (int j = 0; j < 8; j++)
        #pragma unroll
        for (int e = 0; e < 4; e++) oacc[j][e] = 0.f;

    const int T = SEQ / BKV;   // 32
    for (int t = 0; t < T; t++) {
        int buf = t & (NKV - 1);
        asm volatile("cp.async.wait_group 2;");
        __syncthreads();

        if (t + 3 < T) {
            issue(t + 3);
            if (tid < 64) {
                int st = (t + 3) & (NKV - 1);
                int m = maskb[(t + 3) * BKV + tid];
                ms[st * 64 + tid] = m;
                int all = __all_sync(0xffffffffu, m != 0);
                if ((tid & 31) == 0) fl[st * 2 + (tid >> 5)] = all;
            }
        }

        uint32_t kb = ksb + (uint32_t)(buf * BKV * KP) * 2u + kLm;
        uint32_t vb = vsb + (uint32_t)(buf * BKV * VP) * 2u + vLm;
        const int* mb = ms + buf * 64;
        bool allone = fl[buf * 2] && fl[buf * 2 + 1];

        // ---- S = Q @ K^T; k-outer so the 8 MMAs per kk are independent ----
        float sacc[8][4];
        #pragma unroll
        for (int j = 0; j < 8; j++)
            #pragma unroll
            for (int e = 0; e < 4; e++) sacc[j][e] = 0.f;

        #pragma unroll
        for (int kk = 0; kk < 4; kk++) {
            uint32_t kByte = (uint32_t)(kk * 16) * 2u;
            uint32_t bf[8][2];
            #pragma unroll
            for (int jp = 0; jp < 4; jp++)
                LDMX4(bf[2*jp][0], bf[2*jp][1], bf[2*jp+1][0], bf[2*jp+1][1],
                      kb + (uint32_t)(jp * 16 * KP) * 2u + kByte);
            #pragma unroll
            for (int j = 0; j < 8; j++)
                mma_f16(sacc[j][0], sacc[j][1], sacc[j][2], sacc[j][3],
                        afq[kk][0], afq[kk][1], afq[kk][2], afq[kk][3],
                        bf[j][0], bf[j][1]);
        }

        if (!allone) {
            #pragma unroll
            for (int j = 0; j < 8; j++) {
                int col = j * 8 + 2 * c4;
                int mk0 = mb[col], mk1 = mb[col + 1];
                if (!mk0) { sacc[j][0] = -1e9f; sacc[j][2] = -1e9f; }
                if (!mk1) { sacc[j][1] = -1e9f; sacc[j][3] = -1e9f; }
            }
        }

        float rmax0 = -1e30f, rmax1 = -1e30f;
        #pragma unroll
        for (int j = 0; j < 8; j++) {
            rmax0 = fmaxf(rmax0, fmaxf(sacc[j][0], sacc[j][1]));
            rmax1 = fmaxf(rmax1, fmaxf(sacc[j][2], sacc[j][3]));
        }
        rmax0 = fmaxf(rmax0, __shfl_xor_sync(0xffffffffu, rmax0, 1));
        rmax0 = fmaxf(rmax0, __shfl_xor_sync(0xffffffffu, rmax0, 2));
        rmax1 = fmaxf(rmax1, __shfl_xor_sync(0xffffffffu, rmax1, 1));
        rmax1 = fmaxf(rmax1, __shfl_xor_sync(0xffffffffu, rmax1, 2));

        float mnew0 = fmaxf(m0, rmax0), mnew1 = fmaxf(m1, rmax1);
        float sc0 = ex2(m0 - mnew0), sc1 = ex2(m1 - mnew1);

        float rsum0 = 0.f, rsum1 = 0.f;
        uint32_t ap[4][4];
        #pragma unroll
        for (int j = 0; j < 8; j++) {
            float p0 = ex2(sacc[j][0] - mnew0);
            float p1 = ex2(sacc[j][1] - mnew0);
            float p2 = ex2(sacc[j][2] - mnew1);
            float p3 = ex2(sacc[j][3] - mnew1);
            rsum0 += p0 + p1; rsum1 += p2 + p3;
            int kk = j >> 1, hi = j & 1;
            ap[kk][hi ? 2 : 0] = h2u(__floats2half2_rn(p0, p1));
            ap[kk][hi ? 3 : 1] = h2u(__floats2half2_rn(p2, p3));
        }
        rsum0 += __shfl_xor_sync(0xffffffffu, rsum0, 1);
        rsum0 += __shfl_xor_sync(0xffffffffu, rsum0, 2);
        rsum1 += __shfl_xor_sync(0xffffffffu, rsum1, 1);
        rsum1 += __shfl_xor_sync(0xffffffffu, rsum1, 2);

        l0 = l0 * sc0 + rsum0; m0 = mnew0;
        l1 = l1 * sc1 + rsum1; m1 = mnew1;
        #pragma unroll
        for (int j = 0; j < 8; j++) {
            oacc[j][0] *= sc0; oacc[j][1] *= sc0;
            oacc[j][2] *= sc1; oacc[j][3] *= sc1;
        }

        // ---- O += P @ V; k-outer so the 8 MMAs per kk are independent ----
        #pragma unroll
        for (int kk = 0; kk < 4; kk++) {
            uint32_t kRow = (uint32_t)(kk * 16 * VP) * 2u;
            uint32_t vf[8][2];
            #pragma unroll
            for (int dp = 0; dp < 4; dp++)
                LDMX4T(vf[2*dp][0], vf[2*dp][1], vf[2*dp+1][0], vf[2*dp+1][1],
                       vb + (uint32_t)(dp * 16) * 2u + kRow);
            #pragma unroll
            for (int j = 0; j < 8; j++)
                mma_f16(oacc[j][0], oacc[j][1], oacc[j][2], oacc[j][3],
                        ap[kk][0], ap[kk][1], ap[kk][2], ap[kk][3],
                        vf[j][0], vf[j][1]);
        }
    }

    float inv0 = 1.0f / l0, inv1 = 1.0f / l1;
    __half* op = ctx + (size_t)(b * SEQ + qbase + wq) * D_MODEL + h * DK;
    #pragma unroll
    for (int j = 0; j < 8; j++) {
        int col = j * 8 + 2 * c4;
        *(__half2*)&op[(size_t)(r4    ) * D_MODEL + col] =
            __floats2half2_rn(oacc[j][0] * inv0, oacc[j][1] * inv0);
        *(__half2*)&op[(size_t)(r4 + 8) * D_MODEL + col] =
            __floats2half2_rn(oacc[j][2] * inv1, oacc[j][3] * inv1);
    }
}

// ---------------- launch ---------------------------------------------------
extern "C" void kernel_launch(void* const* d_in, const int* in_sizes, int n_in,
                              void* d_out, int out_size)
{
    const float* src  = (const float*)d_in[0];
    const int*   mask = (const int*)  d_in[1];
    const float* wq   = (const float*)d_in[2];
    const float* wk   = (const float*)d_in[3];
    const float* wv   = (const float*)d_in[4];
    const float* wo   = (const float*)d_in[5];
    const float* w1   = (const float*)d_in[6];
    const float* b1   = (const float*)d_in[7];
    const float* w2   = (const float*)d_in[8];
    const float* b2   = (const float*)d_in[9];
    const float* a1   = (const float*)d_in[10];
    const float* be1  = (const float*)d_in[11];
    const float* a2   = (const float*)d_in[12];
    const float* be2  = (const float*)d_in[13];
    float* out = (float*)d_out;

    __half *xln, *qb, *kb, *vb, *ctx, *x2, *ffh;
    __half *pwq, *pwk, *pwv, *pwo, *pw1, *pw2;
    float *out1;
    cudaGetSymbolAddress((void**)&xln,  h_xln);
    cudaGetSymbolAddress((void**)&qb,   h_q);
    cudaGetSymbolAddress((void**)&kb,   h_k);
    cudaGetSymbolAddress((void**)&vb,   h_v);
    cudaGetSymbolAddress((void**)&ctx,  h_ctx);
    cudaGetSymbolAddress((void**)&x2,   h_x2);
    cudaGetSymbolAddress((void**)&ffh,  h_ffh);
    cudaGetSymbolAddress((void**)&out1, g_out1);
    cudaGetSymbolAddress((void**)&pwq,  h_wq);
    cudaGetSymbolAddress((void**)&pwk,  h_wk);
    cudaGetSymbolAddress((void**)&pwv,  h_wv);
    cudaGetSymbolAddress((void**)&pwo,  h_wo);
    cudaGetSymbolAddress((void**)&pw1,  h_w1);
    cudaGetSymbolAddress((void**)&pw2,  h_w2);

    int gsm = GEMM_SMEM;
    cudaFuncSetAttribute(hgemm<0>, cudaFuncAttributeMaxDynamicSharedMemorySize, gsm);
    cudaFuncSetAttribute(hgemm<1>, cudaFuncAttributeMaxDynamicSharedMemorySize, gsm);
    cudaFuncSetAttribute(hgemm<2>, cudaFuncAttributeMaxDynamicSharedMemorySize, gsm);
    cudaFuncSetAttribute(hgemm<3>, cudaFuncAttributeMaxDynamicSharedMemorySize, gsm);
    cudaFuncSetAttribute(attn_mma, cudaFuncAttributeMaxDynamicSharedMemorySize, ATTN_SMEM);

    // 0) weights -> fp16
    round_weights<<<2048, 256>>>(
        (const float4*)wq, (const float4*)wk, (const float4*)wv, (const float4*)wo,
        (const float4*)w1, (const float4*)w2);

    // 1) LN1 -> half
    ln_kernel<<<MROWS, 256>>>(src, xln, a1, be1);

    // 2) QKV projections (half out; Q scaled by 0.125*log2e)
    hgemm<0><<<dim3(D_MODEL/GBN, MROWS/GBM, 3), 256, gsm>>>(
        xln, pwq, pwk, pwv, qb, kb, vb, nullptr, nullptr, MROWS, D_MODEL, D_MODEL);

    // 3) flash attention
    attn_mma<<<dim3(SEQ/BQ, NH, BATCH), 256, ATTN_SMEM>>>(qb, kb, vb, mask, ctx);

    // 4) O projection + residual (float out)
    hgemm<3><<<dim3(D_MODEL/GBN, MROWS/GBM, 1), 256, gsm>>>(
        ctx, pwo, pwo, pwo, out1, out1, out1, nullptr, src, MROWS, D_MODEL, D_MODEL);

    // 5) LN2 -> half
    ln_kernel<<<MROWS, 256>>>(out1, x2, a2, be2);

    // 6) FFN up (half out)
    hgemm<1><<<dim3(DFF/GBN, MROWS/GBM, 1), 256, gsm>>>(
        x2, pw1, pw1, pw1, ffh, ffh, ffh, b1, nullptr, MROWS, DFF, D_MODEL);

    // 7) FFN down + residual (float out)
    hgemm<2><<<dim3(D_MODEL/GBN, MROWS/GBM, 1), 256, gsm>>>(
        ffh, pw2, pw2, pw2, out, out, out, b2, out1, MROWS, D_MODEL, DFF);
}